// round 2
// baseline (speedup 1.0000x reference)
#include <cuda_runtime.h>
#include <math.h>

// Problem constants
#define BB 4
#define SS 4096
#define DM 1024
#define HH 16
#define HD 64
#define MTOT (BB*SS)            // 16384
#define NEL (MTOT*DM)           // 16,777,216 elements per [B,S,D] tensor
#define EPS 1e-6f
#define NBH (BB*HH)             // 64
#define NSPLIT 8                // s-splits for KV accumulation

// -------- scratch (device globals; no allocation allowed) --------
__device__ float g_proj[3 * NEL];              // q,k,v projections
__device__ float g_conv[3 * NEL];              // conv(+fmap) outputs
__device__ float g_vnew[NEL];                  // attention output pre-O-proj
__device__ float g_KVpart[NSPLIT * NBH * HD * HD];
__device__ float g_Ksump[NSPLIT * NBH * HD];
__device__ float g_KV[NBH * HD * HD];
__device__ float g_Ksum[NBH * HD];

// ============================================================
// GEMM: C[M,N] = A[M,K] @ W[N,K]^T + bias[N]
// 128x128 tile, BK=8, 256 threads, 8x8 micro-tile per thread.
// M=16384, N=1024, K=1024 (all divisible; no bounds checks).
// ============================================================
__global__ __launch_bounds__(256)
void gemm_bias_kernel(const float* __restrict__ A,
                      const float* __restrict__ W,
                      const float* __restrict__ bias,
                      float* __restrict__ C, int K)
{
    __shared__ __align__(16) float As[8][128];
    __shared__ __align__(16) float Bs[8][128];

    const int tid = threadIdx.x;
    const int bm0 = blockIdx.y * 128;
    const int bn0 = blockIdx.x * 128;

    const int lrow = tid >> 1;          // 0..127
    const int lk   = (tid & 1) * 4;     // 0 or 4

    const float* Ap = A + (size_t)(bm0 + lrow) * K + lk;
    const float* Wp = W + (size_t)(bn0 + lrow) * K + lk;

    const int tx = tid & 15;            // 0..15 (n)
    const int ty = tid >> 4;            // 0..15 (m)

    float acc[8][8];
#pragma unroll
    for (int i = 0; i < 8; i++)
#pragma unroll
        for (int j = 0; j < 8; j++) acc[i][j] = 0.f;

    for (int k0 = 0; k0 < K; k0 += 8) {
        float4 av = *(const float4*)(Ap + k0);
        float4 wv = *(const float4*)(Wp + k0);
        As[lk + 0][lrow] = av.x; As[lk + 1][lrow] = av.y;
        As[lk + 2][lrow] = av.z; As[lk + 3][lrow] = av.w;
        Bs[lk + 0][lrow] = wv.x; Bs[lk + 1][lrow] = wv.y;
        Bs[lk + 2][lrow] = wv.z; Bs[lk + 3][lrow] = wv.w;
        __syncthreads();

#pragma unroll
        for (int kk = 0; kk < 8; kk++) {
            float a[8], b[8];
            float4 a0 = *(const float4*)&As[kk][ty * 4];
            float4 a1 = *(const float4*)&As[kk][64 + ty * 4];
            float4 b0 = *(const float4*)&Bs[kk][tx * 4];
            float4 b1 = *(const float4*)&Bs[kk][64 + tx * 4];
            a[0]=a0.x; a[1]=a0.y; a[2]=a0.z; a[3]=a0.w;
            a[4]=a1.x; a[5]=a1.y; a[6]=a1.z; a[7]=a1.w;
            b[0]=b0.x; b[1]=b0.y; b[2]=b0.z; b[3]=b0.w;
            b[4]=b1.x; b[5]=b1.y; b[6]=b1.z; b[7]=b1.w;
#pragma unroll
            for (int i = 0; i < 8; i++)
#pragma unroll
                for (int j = 0; j < 8; j++)
                    acc[i][j] += a[i] * b[j];
        }
        __syncthreads();
    }

#pragma unroll
    for (int i = 0; i < 8; i++) {
        int row = bm0 + ((i < 4) ? (ty * 4 + i) : (64 + ty * 4 + i - 4));
#pragma unroll
        for (int j = 0; j < 8; j++) {
            int col = bn0 + ((j < 4) ? (tx * 4 + j) : (64 + tx * 4 + j - 4));
            C[(size_t)row * DM + col] = acc[i][j] + bias[col];
        }
    }
}

// ============================================================
// Depthwise causal conv (KS=3) + optional feature map (elu+1)
// x: [B,S,DM], channel c -> head dim d = c % 64
// y[b,s,c] = bias[d] + w[d,0]*x[s-2] + w[d,1]*x[s-1] + w[d,2]*x[s]
// fmap: v>0 ? v+1 : exp(v)
// ============================================================
__global__ void conv_fmap_kernel(const float* __restrict__ x,
                                 const float* __restrict__ w,
                                 const float* __restrict__ bias,
                                 float* __restrict__ y, int do_fmap)
{
    int idx = blockIdx.x * blockDim.x + threadIdx.x;   // 0..NEL-1
    int c = idx & (DM - 1);
    int d = c & (HD - 1);
    int s = (idx >> 10) & (SS - 1);

    float v = bias[d] + w[d * 3 + 2] * x[idx];
    if (s >= 1) v += w[d * 3 + 1] * x[idx - DM];
    if (s >= 2) v += w[d * 3 + 0] * x[idx - 2 * DM];
    if (do_fmap) v = (v > 0.f) ? (v + 1.f) : expf(v);
    y[idx] = v;
}

// ============================================================
// KV partial accumulation: KVpart[split][bh][d][e] = sum_{s in split} K[s,d]*V[s,e]
// Deterministic (no atomics). 64 bh x NSPLIT blocks, 256 threads.
// Thread owns d = t>>2, e = (t&3) + 4*j (j=0..15).
// ============================================================
__global__ __launch_bounds__(256)
void kv_accum_kernel(const float* __restrict__ kbuf,
                     const float* __restrict__ vbuf)
{
    const int bh = blockIdx.x;
    const int b = bh / HH, h = bh % HH;
    const int split = blockIdx.y;

    __shared__ float Ks[32][64];
    __shared__ float Vs[32][64];

    const int t = threadIdx.x;
    const int d = t >> 2;
    const int e0 = t & 3;

    float acc[16];
#pragma unroll
    for (int j = 0; j < 16; j++) acc[j] = 0.f;
    float ksum = 0.f;

    const size_t base = (size_t)b * SS * DM + h * HD;
    const int sbeg = split * (SS / NSPLIT);

    for (int s0 = sbeg; s0 < sbeg + SS / NSPLIT; s0 += 32) {
#pragma unroll
        for (int r = 0; r < 8; r++) {
            int li = r * 256 + t;
            int ls = li >> 6, ld = li & 63;
            size_t g = base + (size_t)(s0 + ls) * DM + ld;
            Ks[ls][ld] = kbuf[g];
            Vs[ls][ld] = vbuf[g];
        }
        __syncthreads();
#pragma unroll 4
        for (int s = 0; s < 32; s++) {
            float kd = Ks[s][d];
            ksum += kd;
#pragma unroll
            for (int j = 0; j < 16; j++)
                acc[j] += kd * Vs[s][e0 + 4 * j];
        }
        __syncthreads();
    }

    float* kvout = g_KVpart + (((size_t)split * NBH + bh) * HD + d) * HD;
#pragma unroll
    for (int j = 0; j < 16; j++) kvout[e0 + 4 * j] = acc[j];
    if (e0 == 0) g_Ksump[((size_t)split * NBH + bh) * HD + d] = ksum;
}

// Reduce the NSPLIT partials
__global__ void kv_reduce_kernel()
{
    int i = blockIdx.x * blockDim.x + threadIdx.x;   // 0..NBH*HD*HD-1
    float s = 0.f;
#pragma unroll
    for (int p = 0; p < NSPLIT; p++) s += g_KVpart[(size_t)p * NBH * HD * HD + i];
    g_KV[i] = s;
    if (i < NBH * HD) {
        float s2 = 0.f;
#pragma unroll
        for (int p = 0; p < NSPLIT; p++) s2 += g_Ksump[p * NBH * HD + i];
        g_Ksum[i] = s2;
    }
}

// ============================================================
// V_new[b,s,h,e] = (sum_d KV[d,e] * Q[s,d]) / (sum_d Q[s,d]*(Ksum[d]+eps))
// Block: one (b,h) x 32 s-positions. 256 threads: 8 threads per s, 8 e each.
// ============================================================
__global__ __launch_bounds__(256)
void vnew_kernel(const float* __restrict__ qbuf, float* __restrict__ out)
{
    const int bh = blockIdx.x;
    const int b = bh / HH, h = bh % HH;
    const int s0 = blockIdx.y * 32;

    __shared__ float KVs[64 * 64];
    __shared__ float Kss[64];
    __shared__ float Qs[32][64];

    const int t = threadIdx.x;

    const float* kvsrc = g_KV + (size_t)bh * HD * HD;
#pragma unroll
    for (int r = 0; r < 16; r++) KVs[r * 256 + t] = kvsrc[r * 256 + t];
    if (t < 64) Kss[t] = g_Ksum[bh * HD + t] + EPS;

    const size_t base = ((size_t)b * SS + s0) * DM + h * HD;
#pragma unroll
    for (int r = 0; r < 8; r++) {
        int li = r * 256 + t;
        int ls = li >> 6, ld = li & 63;
        Qs[ls][ld] = qbuf[base + (size_t)ls * DM + ld];
    }
    __syncthreads();

    const int sl = t >> 3;          // 0..31
    const int e0 = (t & 7) * 8;     // 0,8,...,56

    float denom = 0.f;
#pragma unroll
    for (int dd = 0; dd < 64; dd++) denom += Qs[sl][dd] * Kss[dd];
    float zinv = 1.f / denom;

    float acc[8];
#pragma unroll
    for (int j = 0; j < 8; j++) acc[j] = 0.f;
#pragma unroll
    for (int dd = 0; dd < 64; dd++) {
        float qd = Qs[sl][dd];
#pragma unroll
        for (int j = 0; j < 8; j++) acc[j] += KVs[dd * 64 + e0 + j] * qd;
    }

    size_t ob = base + (size_t)sl * DM + e0;
#pragma unroll
    for (int j = 0; j < 8; j++) out[ob + j] = acc[j] * zinv;
}

// ============================================================
extern "C" void kernel_launch(void* const* d_in, const int* in_sizes, int n_in,
                              void* d_out, int out_size)
{
    const float* query = (const float*)d_in[0];
    const float* key   = (const float*)d_in[1];
    const float* value = (const float*)d_in[2];
    const float* q_w   = (const float*)d_in[3];
    const float* q_b   = (const float*)d_in[4];
    const float* k_w   = (const float*)d_in[5];
    const float* k_b   = (const float*)d_in[6];
    const float* v_w   = (const float*)d_in[7];
    const float* v_b   = (const float*)d_in[8];
    const float* o_w   = (const float*)d_in[9];
    const float* o_b   = (const float*)d_in[10];
    const float* qc_w  = (const float*)d_in[11];
    const float* qc_b  = (const float*)d_in[12];
    const float* kc_w  = (const float*)d_in[13];
    const float* kc_b  = (const float*)d_in[14];
    const float* vc_w  = (const float*)d_in[15];
    const float* vc_b  = (const float*)d_in[16];
    float* out = (float*)d_out;

    float *proj, *conv, *vnew;
    cudaGetSymbolAddress((void**)&proj, g_proj);
    cudaGetSymbolAddress((void**)&conv, g_conv);
    cudaGetSymbolAddress((void**)&vnew, g_vnew);
    float* pq = proj;           float* pk = proj + (size_t)NEL;  float* pv = proj + 2 * (size_t)NEL;
    float* cq = conv;           float* ck = conv + (size_t)NEL;  float* cv = conv + 2 * (size_t)NEL;

    dim3 ggrid(DM / 128, MTOT / 128);   // (8, 128)

    // 1) QKV projections
    gemm_bias_kernel<<<ggrid, 256>>>(query, q_w, q_b, pq, DM);
    gemm_bias_kernel<<<ggrid, 256>>>(key,   k_w, k_b, pk, DM);
    gemm_bias_kernel<<<ggrid, 256>>>(value, v_w, v_b, pv, DM);

    // 2) depthwise causal conv (+fmap for q,k)
    conv_fmap_kernel<<<NEL / 256, 256>>>(pq, qc_w, qc_b, cq, 1);
    conv_fmap_kernel<<<NEL / 256, 256>>>(pk, kc_w, kc_b, ck, 1);
    conv_fmap_kernel<<<NEL / 256, 256>>>(pv, vc_w, vc_b, cv, 0);

    // 3) KV = K^T V and Ksum (deterministic split + reduce)
    kv_accum_kernel<<<dim3(NBH, NSPLIT), 256>>>(ck, cv);
    kv_reduce_kernel<<<(NBH * HD * HD) / 256, 256>>>();

    // 4) V_new
    vnew_kernel<<<dim3(NBH, SS / 32), 256>>>(cq, vnew);

    // 5) output projection
    gemm_bias_kernel<<<ggrid, 256>>>(vnew, o_w, o_b, out, DM);
}

// round 7
// speedup vs baseline: 3.8035x; 3.8035x over previous
#include <cuda_runtime.h>
#include <math.h>
#include <stdint.h>

// Problem constants
#define BB 4
#define SS 4096
#define DM 1024
#define HH 16
#define HD 64
#define MTOT (BB*SS)            // 16384
#define NEL (MTOT*DM)           // 16,777,216
#define EPS 1e-6f
#define NBH (BB*HH)             // 64
#define NSPLIT 8

// ---- arch-feature detection: tcgen05 needs the 'a' (or family 'f') target ----
#if defined(__CUDA_ARCH_FEAT_SM103_ALL) || defined(__CUDA_ARCH_FEAT_SM100_ALL) || \
    (defined(__CUDA_ARCH_SPECIFIC__) && (__CUDA_ARCH_SPECIFIC__ == 1030 || __CUDA_ARCH_SPECIFIC__ == 1000)) || \
    (defined(__CUDA_ARCH_FAMILY_SPECIFIC__) && (__CUDA_ARCH_FAMILY_SPECIFIC__ == 1030 || __CUDA_ARCH_FAMILY_SPECIFIC__ == 1000))
#define HAS_TC 1
#else
#define HAS_TC 0
#endif

// tcgen05 GEMM tiling
#define TM 128
#define TN 256
#define BK 32                   // floats per k-chunk = 128 bytes (one SW128 row)
#define NK (DM/BK)              // 32
#define NST 4                   // pipeline stages
#define A_STAGE_BYTES (TM*128)  // 16 KB
#define B_STAGE_BYTES (TN*128)  // 32 KB
#define STAGE_BYTES (A_STAGE_BYTES + B_STAGE_BYTES)   // 48 KB
#define SMEM_STAGE0 2048
#define GEMM_SMEM (SMEM_STAGE0 + NST*STAGE_BYTES)     // 198656

// mma.sync fallback tiling: 128x128 tile, 256 threads, 2-stage cp.async
#define MMA_SMEM (4*128*36*4)   // 73728 bytes (A,B x 2 stages, pad 36)

// -------- scratch (device globals) --------
__device__ float g_proj[3 * NEL];
__device__ float g_conv[3 * NEL];
__device__ float g_vnew[NEL];
__device__ float g_rw[4 * DM * DM];
__device__ float g_KVpart[NSPLIT * NBH * HD * HD];
__device__ float g_Ksump[NSPLIT * NBH * HD];
__device__ float g_KV[NBH * HD * HD];
__device__ float g_Ksum[NBH * HD];

// ============================================================
// PTX helpers (all baseline-PTX unless noted)
// ============================================================
__device__ __forceinline__ uint32_t smem_u32(const void* p) {
    uint32_t a;
    asm("{ .reg .u64 t; cvta.to.shared.u64 t, %1; cvt.u32.u64 %0, t; }" : "=r"(a) : "l"(p));
    return a;
}
#define SWZ(o) ((o) ^ (((o) >> 3) & 0x70))

#define CP_ASYNC16(dst, src) \
    asm volatile("cp.async.cg.shared.global [%0], [%1], 16;" :: "r"(dst), "l"(src) : "memory")
#define CP_COMMIT() asm volatile("cp.async.commit_group;" ::: "memory")
#define CP_WAIT3()  asm volatile("cp.async.wait_group 3;" ::: "memory")
#define CP_WAIT1()  asm volatile("cp.async.wait_group 1;" ::: "memory")

#define MBAR_INIT(addr, cnt) \
    asm volatile("mbarrier.init.shared.b64 [%0], %1;" :: "r"(addr), "r"(cnt) : "memory")
__device__ __forceinline__ void mbar_wait(uint32_t addr, uint32_t phase) {
    asm volatile(
        "{\n\t.reg .pred P;\n\t"
        "W_%=:\n\t"
        "mbarrier.try_wait.parity.shared.b64 P, [%0], %1, 0x989680;\n\t"
        "@P bra D_%=;\n\t"
        "bra W_%=;\n\t"
        "D_%=:\n\t}"
        :: "r"(addr), "r"(phase) : "memory");
}

// tf32 rounding (sm_80+ baseline)
__device__ __forceinline__ float rtf(float x) {
    asm("cvt.rna.tf32.f32 %0, %0;" : "+f"(x));
    return x;
}

// mma.sync tf32 (sm_80+ baseline)
#define MMA_TF32(c, a, b) \
    asm volatile("mma.sync.aligned.m16n8k8.row.col.f32.tf32.tf32.f32 " \
        "{%0,%1,%2,%3}, {%4,%5,%6,%7}, {%8,%9}, {%0,%1,%2,%3};" \
        : "+f"((c)[0]), "+f"((c)[1]), "+f"((c)[2]), "+f"((c)[3]) \
        : "r"((a)[0]), "r"((a)[1]), "r"((a)[2]), "r"((a)[3]), \
          "r"((b)[0]), "r"((b)[1]))

#if HAS_TC
// ---- tcgen05-only macros (expand only inside HAS_TC-guarded bodies) ----
#define TC_ALLOC(sm, n)   asm volatile("tcgen05.alloc.cta_group::1.sync.aligned.shared::cta.b32 [%0], %1;" :: "r"(sm), "r"(n) : "memory")
#define TC_DEALLOC(t, n)  asm volatile("tcgen05.dealloc.cta_group::1.sync.aligned.b32 %0, %1;" :: "r"(t), "r"(n))
#define TC_RELINQ()       asm volatile("tcgen05.relinquish_alloc_permit.cta_group::1.sync.aligned;")
#define TC_COMMIT(mb)     asm volatile("tcgen05.commit.cta_group::1.mbarrier::arrive::one.shared::cluster.b64 [%0];" :: "r"(mb) : "memory")
#define TC_FENCE_AFTER()  asm volatile("tcgen05.fence::after_thread_sync;" ::: "memory")
#define TC_WAIT_LD()      asm volatile("tcgen05.wait::ld.sync.aligned;" ::: "memory")
#define FENCE_PROXY()     asm volatile("fence.proxy.async.shared::cta;" ::: "memory")

#define TC_LD_X32(r, ta) \
    asm volatile( \
        "tcgen05.ld.sync.aligned.32x32b.x32.b32 " \
        "{%0, %1, %2, %3, %4, %5, %6, %7, " \
        " %8, %9, %10, %11, %12, %13, %14, %15, " \
        " %16, %17, %18, %19, %20, %21, %22, %23, " \
        " %24, %25, %26, %27, %28, %29, %30, %31}, [%32];" \
        : "=r"((r)[0]),  "=r"((r)[1]),  "=r"((r)[2]),  "=r"((r)[3]), \
          "=r"((r)[4]),  "=r"((r)[5]),  "=r"((r)[6]),  "=r"((r)[7]), \
          "=r"((r)[8]),  "=r"((r)[9]),  "=r"((r)[10]), "=r"((r)[11]), \
          "=r"((r)[12]), "=r"((r)[13]), "=r"((r)[14]), "=r"((r)[15]), \
          "=r"((r)[16]), "=r"((r)[17]), "=r"((r)[18]), "=r"((r)[19]), \
          "=r"((r)[20]), "=r"((r)[21]), "=r"((r)[22]), "=r"((r)[23]), \
          "=r"((r)[24]), "=r"((r)[25]), "=r"((r)[26]), "=r"((r)[27]), \
          "=r"((r)[28]), "=r"((r)[29]), "=r"((r)[30]), "=r"((r)[31]) \
        : "r"(ta))

__device__ __forceinline__ uint64_t make_desc(uint32_t addr) {
    const uint64_t base =
        (uint64_t(2)  << 61) | (uint64_t(1) << 46) | (uint64_t(64) << 32) | (uint64_t(1) << 16);
    return base | ((uint64_t)(addr >> 4) & 0x3FFF);
}

__device__ __forceinline__ void mma_tf32_ss(uint32_t d_tmem, uint64_t a_desc, uint64_t b_desc,
                                            uint32_t idesc, uint32_t enable) {
    asm volatile(
        "{\n\t"
        ".reg .pred p;\n\t"
        "setp.ne.u32 p, %4, 0;\n\t"
        "tcgen05.mma.cta_group::1.kind::tf32 [%0], %1, %2, %3, {%5, %5, %5, %5}, p;\n\t"
        "}"
        :: "r"(d_tmem), "l"(a_desc), "l"(b_desc), "r"(idesc), "r"(enable), "r"(0u)
        : "memory");
}
#endif  // HAS_TC

// ============================================================
// Path A: tcgen05 tf32 GEMM: C[M,N] = A[M,K] @ W[N,K]^T + bias[N]
// Tile 128x256, 128 threads/CTA. Empty body on non-'a' targets.
// ============================================================
__global__ __launch_bounds__(128, 1)
void gemm_tf32_kernel(const float* __restrict__ A,
                      const float* __restrict__ W,
                      const float* __restrict__ bias,
                      float* __restrict__ C)
{
#if HAS_TC
    extern __shared__ __align__(1024) char smem[];
    const uint32_t sb = smem_u32(smem);
    const int tid = threadIdx.x;
    const int wid = tid >> 5, lid = tid & 31;
    const int bm0 = blockIdx.y * TM;
    const int bn0 = blockIdx.x * TN;

    float* bsm = (float*)(smem + 128);
    bsm[tid] = bias[bn0 + tid];
    bsm[tid + 128] = bias[bn0 + 128 + tid];

    if (wid == 0) TC_ALLOC(sb + 0, 256);
    if (tid == 0) {
        for (int s = 0; s < NST; s++) MBAR_INIT(sb + 16 + s * 8, 1);
        MBAR_INIT(sb + 16 + NST * 8, 1);
    }
    __syncthreads();
    uint32_t tmem;
    asm volatile("ld.shared.b32 %0, [%1];" : "=r"(tmem) : "r"(sb + 0));

    const float* Abase = A + (size_t)bm0 * DM;
    const float* Wbase = W + (size_t)bn0 * DM;

    const uint32_t idesc = (1u << 4)        // dtype F32
                         | (2u << 7)        // atype TF32
                         | (2u << 10)       // btype TF32
                         | ((TN / 8) << 17)
                         | ((TM / 16) << 24);

    // prologue: stages 0..NST-2
#pragma unroll
    for (int j = 0; j < NST - 1; j++) {
        uint32_t abase = sb + SMEM_STAGE0 + j * STAGE_BYTES;
        uint32_t bbase = abase + A_STAGE_BYTES;
#pragma unroll
        for (int r = 0; r < 8; r++) {
            int i = tid + r * 128; int row = i >> 3, c16 = i & 7;
            CP_ASYNC16(abase + SWZ(row * 128 + c16 * 16),
                       Abase + (size_t)row * DM + j * BK + c16 * 4);
        }
#pragma unroll
        for (int r = 0; r < 16; r++) {
            int i = tid + r * 128; int row = i >> 3, c16 = i & 7;
            CP_ASYNC16(bbase + SWZ(row * 128 + c16 * 16),
                       Wbase + (size_t)row * DM + j * BK + c16 * 4);
        }
        CP_COMMIT();
    }

    for (int kc = 0; kc < NK; kc++) {
        const int j = kc + NST - 1;
        if (j < NK) {
            const int sl = j & (NST - 1);
            if (j >= NST) mbar_wait(sb + 16 + sl * 8, ((j >> 2) - 1) & 1);
            uint32_t abase = sb + SMEM_STAGE0 + sl * STAGE_BYTES;
            uint32_t bbase = abase + A_STAGE_BYTES;
#pragma unroll
            for (int r = 0; r < 8; r++) {
                int i = tid + r * 128; int row = i >> 3, c16 = i & 7;
                CP_ASYNC16(abase + SWZ(row * 128 + c16 * 16),
                           Abase + (size_t)row * DM + j * BK + c16 * 4);
            }
#pragma unroll
            for (int r = 0; r < 16; r++) {
                int i = tid + r * 128; int row = i >> 3, c16 = i & 7;
                CP_ASYNC16(bbase + SWZ(row * 128 + c16 * 16),
                           Wbase + (size_t)row * DM + j * BK + c16 * 4);
            }
        }
        CP_COMMIT();
        CP_WAIT3();
        __syncthreads();
        if (tid == 0) {
            FENCE_PROXY();
            const int sl = kc & (NST - 1);
            uint32_t abase = sb + SMEM_STAGE0 + sl * STAGE_BYTES;
            uint64_t ad = make_desc(abase);
            uint64_t bd = make_desc(abase + A_STAGE_BYTES);
#pragma unroll
            for (int t = 0; t < 4; t++)
                mma_tf32_ss(tmem, ad + t * 2, bd + t * 2, idesc, (uint32_t)((kc | t) != 0));
            TC_COMMIT(sb + 16 + sl * 8);
        }
    }
    if (tid == 0) TC_COMMIT(sb + 16 + NST * 8);
    mbar_wait(sb + 16 + NST * 8, 0);
    TC_FENCE_AFTER();

    // epilogue: TMEM -> smem -> gmem, 4 chunks of 64 cols
    float* stg = (float*)(smem + SMEM_STAGE0);
    const int m = wid * 32 + lid;
#pragma unroll 1
    for (int ch = 0; ch < 4; ch++) {
        uint32_t r[64];
        TC_LD_X32(r, tmem + ch * 64);
        TC_LD_X32(r + 32, tmem + ch * 64 + 32);
        TC_WAIT_LD();
        __syncthreads();
#pragma unroll
        for (int c = 0; c < 64; c++)
            stg[m * 65 + c] = __uint_as_float(r[c]) + bsm[ch * 64 + c];
        __syncthreads();
        size_t cb = (size_t)bm0 * DM + bn0 + ch * 64;
#pragma unroll 8
        for (int it = 0; it < 64; it++) {
            int i = tid + it * 128;
            int mm = i >> 6, cc = i & 63;
            C[cb + (size_t)mm * DM + cc] = stg[mm * 65 + cc];
        }
    }
    __syncthreads();
    if (wid == 0) { TC_RELINQ(); TC_DEALLOC(tmem, 256); }
#else
    (void)A; (void)W; (void)bias; (void)C;
#endif
}

// ============================================================
// Path B: mma.sync tf32 fallback GEMM (baseline PTX, sm_80+)
// Tile 128x128, 256 threads (8 warps; warp tile 32x64), 2-stage cp.async.
// Empty body when tcgen05 is available (Path A handles it).
// ============================================================
__global__ __launch_bounds__(256, 1)
void gemm_mma_kernel(const float* __restrict__ A,
                     const float* __restrict__ W,
                     const float* __restrict__ bias,
                     float* __restrict__ C)
{
#if defined(__CUDA_ARCH__) && !HAS_TC
    extern __shared__ __align__(16) float fsm[];
    float* As = fsm;                     // [2][128][36]
    float* Bs = fsm + 2 * 128 * 36;      // [2][128][36]
    const uint32_t as_u = smem_u32(As);
    const uint32_t bs_u = smem_u32(Bs);

    const int tid = threadIdx.x;
    const int lane = tid & 31, warp = tid >> 5;
    const int wm = warp & 3;             // 0..3 -> 32 rows each
    const int wn = warp >> 2;            // 0..1 -> 64 cols each
    const int g = lane >> 2, ti = lane & 3;
    const int bm0 = blockIdx.y * 128;
    const int bn0 = blockIdx.x * 128;

    const float* Ag = A + (size_t)bm0 * DM;
    const float* Wg = W + (size_t)bn0 * DM;

    float c[2][8][4];
#pragma unroll
    for (int mi = 0; mi < 2; mi++)
#pragma unroll
        for (int ni = 0; ni < 8; ni++)
#pragma unroll
            for (int q = 0; q < 4; q++) c[mi][ni][q] = 0.f;

    auto load = [&](int st, int kc) {
        uint32_t ab = as_u + st * (128 * 36 * 4);
        uint32_t bb = bs_u + st * (128 * 36 * 4);
        const float* Ak = Ag + kc * 32;
        const float* Wk = Wg + kc * 32;
#pragma unroll
        for (int r = 0; r < 4; r++) {
            int i = tid + r * 256; int row = i >> 3, cc = i & 7;
            CP_ASYNC16(ab + row * 144 + cc * 16, Ak + (size_t)row * DM + cc * 4);
            CP_ASYNC16(bb + row * 144 + cc * 16, Wk + (size_t)row * DM + cc * 4);
        }
    };

    load(0, 0); CP_COMMIT();
    for (int kc = 0; kc < DM / 32; kc++) {
        if (kc + 1 < DM / 32) load((kc + 1) & 1, kc + 1);
        CP_COMMIT();
        CP_WAIT1();
        __syncthreads();
        const float* as_ = As + (kc & 1) * 128 * 36;
        const float* bs_ = Bs + (kc & 1) * 128 * 36;
#pragma unroll
        for (int ks = 0; ks < 4; ks++) {
            uint32_t a[2][4], b[8][2];
#pragma unroll
            for (int mi = 0; mi < 2; mi++) {
                int r0 = wm * 32 + mi * 16 + g;
                a[mi][0] = __float_as_uint(as_[r0 * 36 + ks * 8 + ti]);
                a[mi][1] = __float_as_uint(as_[(r0 + 8) * 36 + ks * 8 + ti]);
                a[mi][2] = __float_as_uint(as_[r0 * 36 + ks * 8 + ti + 4]);
                a[mi][3] = __float_as_uint(as_[(r0 + 8) * 36 + ks * 8 + ti + 4]);
            }
#pragma unroll
            for (int ni = 0; ni < 8; ni++) {
                int n0 = wn * 64 + ni * 8 + g;
                b[ni][0] = __float_as_uint(bs_[n0 * 36 + ks * 8 + ti]);
                b[ni][1] = __float_as_uint(bs_[n0 * 36 + ks * 8 + ti + 4]);
            }
#pragma unroll
            for (int mi = 0; mi < 2; mi++)
#pragma unroll
                for (int ni = 0; ni < 8; ni++)
                    MMA_TF32(c[mi][ni], a[mi], b[ni]);
        }
        __syncthreads();
    }

#pragma unroll
    for (int mi = 0; mi < 2; mi++) {
        int r0 = bm0 + wm * 32 + mi * 16 + g;
#pragma unroll
        for (int ni = 0; ni < 8; ni++) {
            int c0 = bn0 + wn * 64 + ni * 8 + ti * 2;
            float b0 = bias[c0], b1 = bias[c0 + 1];
            C[(size_t)r0 * DM + c0]           = c[mi][ni][0] + b0;
            C[(size_t)r0 * DM + c0 + 1]       = c[mi][ni][1] + b1;
            C[(size_t)(r0 + 8) * DM + c0]     = c[mi][ni][2] + b0;
            C[(size_t)(r0 + 8) * DM + c0 + 1] = c[mi][ni][3] + b1;
        }
    }
#else
    (void)A; (void)W; (void)bias; (void)C;
#endif
}

// ============================================================
// Round fp32 -> tf32 (RN), vectorized
// ============================================================
__global__ void round_tf32_kernel(const float4* __restrict__ x, float4* __restrict__ y)
{
    int i = blockIdx.x * blockDim.x + threadIdx.x;
    float4 v = x[i];
    v.x = rtf(v.x); v.y = rtf(v.y); v.z = rtf(v.z); v.w = rtf(v.w);
    y[i] = v;
}

// ============================================================
// Depthwise causal conv (KS=3) + optional feature map, float4
// ============================================================
__global__ void conv_fmap_kernel(const float4* __restrict__ x,
                                 const float* __restrict__ w,
                                 const float* __restrict__ bias,
                                 float4* __restrict__ y, int do_fmap)
{
    int i = blockIdx.x * blockDim.x + threadIdx.x;
    int c4 = i & 255;
    int s = (i >> 8) & (SS - 1);
    int d0 = (c4 * 4) & (HD - 1);

    float4 x0 = x[i];
    float4 x1 = (s >= 1) ? x[i - 256] : make_float4(0.f, 0.f, 0.f, 0.f);
    float4 x2 = (s >= 2) ? x[i - 512] : make_float4(0.f, 0.f, 0.f, 0.f);

    float4 o;
    o.x = bias[d0+0] + w[(d0+0)*3+2]*x0.x + w[(d0+0)*3+1]*x1.x + w[(d0+0)*3+0]*x2.x;
    o.y = bias[d0+1] + w[(d0+1)*3+2]*x0.y + w[(d0+1)*3+1]*x1.y + w[(d0+1)*3+0]*x2.y;
    o.z = bias[d0+2] + w[(d0+2)*3+2]*x0.z + w[(d0+2)*3+1]*x1.z + w[(d0+2)*3+0]*x2.z;
    o.w = bias[d0+3] + w[(d0+3)*3+2]*x0.w + w[(d0+3)*3+1]*x1.w + w[(d0+3)*3+0]*x2.w;
    if (do_fmap) {
        o.x = (o.x > 0.f) ? (o.x + 1.f) : expf(o.x);
        o.y = (o.y > 0.f) ? (o.y + 1.f) : expf(o.y);
        o.z = (o.z > 0.f) ? (o.z + 1.f) : expf(o.z);
        o.w = (o.w > 0.f) ? (o.w + 1.f) : expf(o.w);
    }
    y[i] = o;
}

// ============================================================
// KV partial accumulation (deterministic split)
// ============================================================
__global__ __launch_bounds__(256)
void kv_accum_kernel(const float* __restrict__ kbuf,
                     const float* __restrict__ vbuf)
{
    const int bh = blockIdx.x;
    const int b = bh / HH, h = bh % HH;
    const int split = blockIdx.y;

    __shared__ float Ks[32][64];
    __shared__ float Vs[32][64];

    const int t = threadIdx.x;
    const int d = t >> 2;
    const int e0 = t & 3;

    float acc[16];
#pragma unroll
    for (int j = 0; j < 16; j++) acc[j] = 0.f;
    float ksum = 0.f;

    const size_t base = (size_t)b * SS * DM + h * HD;
    const int sbeg = split * (SS / NSPLIT);

    for (int s0 = sbeg; s0 < sbeg + SS / NSPLIT; s0 += 32) {
#pragma unroll
        for (int r = 0; r < 8; r++) {
            int li = r * 256 + t;
            int ls = li >> 6, ld = li & 63;
            size_t g = base + (size_t)(s0 + ls) * DM + ld;
            Ks[ls][ld] = kbuf[g];
            Vs[ls][ld] = vbuf[g];
        }
        __syncthreads();
#pragma unroll 4
        for (int s = 0; s < 32; s++) {
            float kd = Ks[s][d];
            ksum += kd;
#pragma unroll
            for (int j = 0; j < 16; j++)
                acc[j] += kd * Vs[s][e0 + 4 * j];
        }
        __syncthreads();
    }

    float* kvout = g_KVpart + (((size_t)split * NBH + bh) * HD + d) * HD;
#pragma unroll
    for (int j = 0; j < 16; j++) kvout[e0 + 4 * j] = acc[j];
    if (e0 == 0) g_Ksump[((size_t)split * NBH + bh) * HD + d] = ksum;
}

__global__ void kv_reduce_kernel()
{
    int i = blockIdx.x * blockDim.x + threadIdx.x;
    float s = 0.f;
#pragma unroll
    for (int p = 0; p < NSPLIT; p++) s += g_KVpart[(size_t)p * NBH * HD * HD + i];
    g_KV[i] = s;
    if (i < NBH * HD) {
        float s2 = 0.f;
#pragma unroll
        for (int p = 0; p < NSPLIT; p++) s2 += g_Ksump[p * NBH * HD + i];
        g_Ksum[i] = s2;
    }
}

// ============================================================
// V_new, output rounded to tf32 (feeds O-proj GEMM)
// ============================================================
__global__ __launch_bounds__(256)
void vnew_kernel(const float* __restrict__ qbuf, float* __restrict__ out)
{
    const int bh = blockIdx.x;
    const int b = bh / HH, h = bh % HH;
    const int s0 = blockIdx.y * 32;

    __shared__ float KVs[64 * 64];
    __shared__ float Kss[64];
    __shared__ float Qs[32][64];

    const int t = threadIdx.x;

    const float* kvsrc = g_KV + (size_t)bh * HD * HD;
#pragma unroll
    for (int r = 0; r < 16; r++) KVs[r * 256 + t] = kvsrc[r * 256 + t];
    if (t < 64) Kss[t] = g_Ksum[bh * HD + t] + EPS;

    const size_t base = ((size_t)b * SS + s0) * DM + h * HD;
#pragma unroll
    for (int r = 0; r < 8; r++) {
        int li = r * 256 + t;
        int ls = li >> 6, ld = li & 63;
        Qs[ls][ld] = qbuf[base + (size_t)ls * DM + ld];
    }
    __syncthreads();

    const int sl = t >> 3;
    const int e0 = (t & 7) * 8;

    float denom = 0.f;
#pragma unroll
    for (int dd = 0; dd < 64; dd++) denom += Qs[sl][dd] * Kss[dd];
    float zinv = 1.f / denom;

    float acc[8];
#pragma unroll
    for (int j = 0; j < 8; j++) acc[j] = 0.f;
#pragma unroll
    for (int dd = 0; dd < 64; dd++) {
        float qd = Qs[sl][dd];
#pragma unroll
        for (int j = 0; j < 8; j++) acc[j] += KVs[dd * 64 + e0 + j] * qd;
    }

    size_t ob = base + (size_t)sl * DM + e0;
#pragma unroll
    for (int j = 0; j < 8; j++) out[ob + j] = rtf(acc[j] * zinv);
}

// ============================================================
extern "C" void kernel_launch(void* const* d_in, const int* in_sizes, int n_in,
                              void* d_out, int out_size)
{
    const float* query = (const float*)d_in[0];
    const float* key   = (const float*)d_in[1];
    const float* value = (const float*)d_in[2];
    const float* q_w   = (const float*)d_in[3];
    const float* q_b   = (const float*)d_in[4];
    const float* k_w   = (const float*)d_in[5];
    const float* k_b   = (const float*)d_in[6];
    const float* v_w   = (const float*)d_in[7];
    const float* v_b   = (const float*)d_in[8];
    const float* o_w   = (const float*)d_in[9];
    const float* o_b   = (const float*)d_in[10];
    const float* qc_w  = (const float*)d_in[11];
    const float* qc_b  = (const float*)d_in[12];
    const float* kc_w  = (const float*)d_in[13];
    const float* kc_b  = (const float*)d_in[14];
    const float* vc_w  = (const float*)d_in[15];
    const float* vc_b  = (const float*)d_in[16];
    float* out = (float*)d_out;

    float *proj, *conv, *vnew, *rw;
    cudaGetSymbolAddress((void**)&proj, g_proj);
    cudaGetSymbolAddress((void**)&conv, g_conv);
    cudaGetSymbolAddress((void**)&vnew, g_vnew);
    cudaGetSymbolAddress((void**)&rw,   g_rw);
    float* pq = proj;  float* pk = proj + (size_t)NEL;  float* pv = proj + 2 * (size_t)NEL;
    float* cq = conv;  float* ck = conv + (size_t)NEL;  float* cv = conv + 2 * (size_t)NEL;
    float* rqw = rw;                       float* rkw = rw + (size_t)DM * DM;
    float* rvw = rw + 2 * (size_t)DM * DM; float* row_ = rw + 3 * (size_t)DM * DM;

    cudaFuncSetAttribute(gemm_tf32_kernel,
                         cudaFuncAttributeMaxDynamicSharedMemorySize, GEMM_SMEM);
    cudaFuncSetAttribute(gemm_mma_kernel,
                         cudaFuncAttributeMaxDynamicSharedMemorySize, MMA_SMEM);

    const int WN4 = (DM * DM) / 4;
    const int IN4 = NEL / 4;

    // 0) round GEMM operands to tf32 (RN)
    round_tf32_kernel<<<IN4 / 256, 256>>>((const float4*)query, (float4*)cq);
    round_tf32_kernel<<<IN4 / 256, 256>>>((const float4*)key,   (float4*)ck);
    round_tf32_kernel<<<IN4 / 256, 256>>>((const float4*)value, (float4*)cv);
    round_tf32_kernel<<<WN4 / 256, 256>>>((const float4*)q_w, (float4*)rqw);
    round_tf32_kernel<<<WN4 / 256, 256>>>((const float4*)k_w, (float4*)rkw);
    round_tf32_kernel<<<WN4 / 256, 256>>>((const float4*)v_w, (float4*)rvw);
    round_tf32_kernel<<<WN4 / 256, 256>>>((const float4*)o_w, (float4*)row_);

    dim3 ggrid_tc(DM / TN, MTOT / TM);    // (4, 128) for tcgen05 path
    dim3 ggrid_mma(DM / 128, MTOT / 128); // (8, 128) for mma.sync path

    // exactly one of each pair does work, chosen at compile time per target
#define LAUNCH_GEMM(Ain, Win, Bias, Cout) do { \
        gemm_tf32_kernel<<<ggrid_tc, 128, GEMM_SMEM>>>(Ain, Win, Bias, Cout); \
        gemm_mma_kernel<<<ggrid_mma, 256, MMA_SMEM>>>(Ain, Win, Bias, Cout); \
    } while (0)

    // 1) QKV projections
    LAUNCH_GEMM(cq, rqw, q_b, pq);
    LAUNCH_GEMM(ck, rkw, k_b, pk);
    LAUNCH_GEMM(cv, rvw, v_b, pv);

    // 2) depthwise causal conv (+fmap for q,k)
    conv_fmap_kernel<<<(NEL / 4) / 256, 256>>>((const float4*)pq, qc_w, qc_b, (float4*)cq, 1);
    conv_fmap_kernel<<<(NEL / 4) / 256, 256>>>((const float4*)pk, kc_w, kc_b, (float4*)ck, 1);
    conv_fmap_kernel<<<(NEL / 4) / 256, 256>>>((const float4*)pv, vc_w, vc_b, (float4*)cv, 0);

    // 3) KV = K^T V and Ksum
    kv_accum_kernel<<<dim3(NBH, NSPLIT), 256>>>(ck, cv);
    kv_reduce_kernel<<<(NBH * HD * HD) / 256, 256>>>();

    // 4) V_new (tf32-rounded output)
    vnew_kernel<<<dim3(NBH, SS / 32), 256>>>(cq, vnew);

    // 5) output projection
    LAUNCH_GEMM(vnew, row_, o_b, out);
#undef LAUNCH_GEMM
}